// round 1
// baseline (speedup 1.0000x reference)
#include <cuda_runtime.h>

#define FDIM 128
#define NN   50000

// ---------------- scratch (device globals: no allocation allowed) ----------
static __device__ float g_deg[NN];
static __device__ float g_agg[(size_t)NN * FDIM];
static __device__ float g_h  [(size_t)NN * FDIM];
static __device__ float g_h2 [(size_t)NN * FDIM];
static __device__ float g_bn [256];    // [0:128) sum, [128:256) sumsq
static __device__ float g_bnab[256];   // [0:128) scale, [128:256) shift
static __device__ int   g_is64;

// ---------------- edge-index dtype detection -------------------------------
__global__ void k_detect(const void* ei) {
    if (threadIdx.x == 0) {
        const int* p = (const int*)ei;
        // int64 little-endian: high words of first two entries are 0.
        g_is64 = (p[1] == 0 && p[3] == 0) ? 1 : 0;
    }
}

// ---------------- zero kernels ---------------------------------------------
__global__ void k_zero_all(int n4, int nd4) {
    int i = blockIdx.x * blockDim.x + threadIdx.x;
    float4 z = make_float4(0.f, 0.f, 0.f, 0.f);
    if (i < n4)  reinterpret_cast<float4*>(g_agg)[i] = z;
    if (i < nd4) reinterpret_cast<float4*>(g_deg)[i] = z;
    if (i < 64)  reinterpret_cast<float4*>(g_bn)[i]  = z;
}
__global__ void k_zero_agg(int n4) {
    int i = blockIdx.x * blockDim.x + threadIdx.x;
    if (i < n4) reinterpret_cast<float4*>(g_agg)[i] = make_float4(0.f, 0.f, 0.f, 0.f);
}

// ---------------- edge scatter: warp per edge, vector red ------------------
template<int SRC, int DEG>
__global__ void k_scatter(const float* __restrict__ xin,
                          const void* __restrict__ ei, int E) {
    int gt   = blockIdx.x * blockDim.x + threadIdx.x;
    int e    = gt >> 5;
    int lane = gt & 31;
    if (e >= E) return;
    const float* src_buf = (SRC == 0) ? xin : g_h;

    long long s, d;
    if (g_is64) {
        s = reinterpret_cast<const long long*>(ei)[e];
        d = reinterpret_cast<const long long*>(ei)[E + e];
    } else {
        s = reinterpret_cast<const int*>(ei)[e];
        d = reinterpret_cast<const int*>(ei)[E + e];
    }

    float4 v = reinterpret_cast<const float4*>(src_buf + (size_t)s * FDIM)[lane];
    float* a = g_agg + (size_t)d * FDIM + lane * 4;
    asm volatile("red.global.add.v4.f32 [%0], {%1,%2,%3,%4};"
                 :: "l"(a), "f"(v.x), "f"(v.y), "f"(v.z), "f"(v.w) : "memory");
    if (DEG && lane == 0) atomicAdd(&g_deg[(int)d], 1.0f);
}

// ---------------- fused SAGE linear + bias + L2-norm (+ReLU) ---------------
// C[64 x 128] per block, 128 threads, 8x8 register tile each.
// K = 256: branch 0 = agg * inv_deg  @ Wl^T, branch 1 = root feats @ Wr^T.
template<int LAYER>
__global__ __launch_bounds__(128)
void k_sage(const float* __restrict__ xin,
            const float* __restrict__ Wl, const float* __restrict__ bl,
            const float* __restrict__ Wr, int n) {
    __shared__ __align__(16) float As[16][64];
    __shared__ __align__(16) float Bs[16][128];
    __shared__ float rowsq[64];

    const float* A2  = (LAYER == 1) ? xin : g_h;
    float*       out = (LAYER == 1) ? g_h : g_h2;

    int t  = threadIdx.x;
    int tx = t & 15;        // col group (8 cols)
    int ty = t >> 4;        // row group (8 rows)
    int row0 = blockIdx.x * 64;

    // loader role: each thread loads 8 consecutive k of one row
    int lrow = t >> 1;
    int lk   = (t & 1) * 8;
    int grow = row0 + lrow;

    float scale = 0.f;
    if (grow < n) {
        float dg = g_deg[grow];
        scale = (dg > 0.f) ? (1.0f / dg) : 0.f;
    }

    float acc[8][8];
#pragma unroll
    for (int i = 0; i < 8; i++)
#pragma unroll
        for (int j = 0; j < 8; j++) acc[i][j] = 0.f;

#pragma unroll 1
    for (int br = 0; br < 2; br++) {
        const float* A = (br == 0) ? g_agg : A2;
        const float* W = (br == 0) ? Wl : Wr;
        float sc = (br == 0) ? scale : 1.0f;
#pragma unroll 1
        for (int kt = 0; kt < FDIM; kt += 16) {
            float4 a0 = make_float4(0.f,0.f,0.f,0.f), a1 = a0;
            if (grow < n) {
                const float4* ap = reinterpret_cast<const float4*>(
                    A + (size_t)grow * FDIM + kt + lk);
                a0 = ap[0]; a1 = ap[1];
            }
            a0.x *= sc; a0.y *= sc; a0.z *= sc; a0.w *= sc;
            a1.x *= sc; a1.y *= sc; a1.z *= sc; a1.w *= sc;

            const float4* wp = reinterpret_cast<const float4*>(W + t * FDIM + kt);
            float4 w0 = wp[0], w1 = wp[1], w2 = wp[2], w3 = wp[3];

            __syncthreads();
            As[lk+0][lrow] = a0.x; As[lk+1][lrow] = a0.y;
            As[lk+2][lrow] = a0.z; As[lk+3][lrow] = a0.w;
            As[lk+4][lrow] = a1.x; As[lk+5][lrow] = a1.y;
            As[lk+6][lrow] = a1.z; As[lk+7][lrow] = a1.w;

            Bs[ 0][t] = w0.x; Bs[ 1][t] = w0.y; Bs[ 2][t] = w0.z; Bs[ 3][t] = w0.w;
            Bs[ 4][t] = w1.x; Bs[ 5][t] = w1.y; Bs[ 6][t] = w1.z; Bs[ 7][t] = w1.w;
            Bs[ 8][t] = w2.x; Bs[ 9][t] = w2.y; Bs[10][t] = w2.z; Bs[11][t] = w2.w;
            Bs[12][t] = w3.x; Bs[13][t] = w3.y; Bs[14][t] = w3.z; Bs[15][t] = w3.w;
            __syncthreads();

#pragma unroll
            for (int k = 0; k < 16; k++) {
                float4 b0 = *reinterpret_cast<const float4*>(&Bs[k][tx * 8]);
                float4 b1 = *reinterpret_cast<const float4*>(&Bs[k][tx * 8 + 4]);
                float4 p0 = *reinterpret_cast<const float4*>(&As[k][ty * 8]);
                float4 p1 = *reinterpret_cast<const float4*>(&As[k][ty * 8 + 4]);
                float aa[8] = {p0.x,p0.y,p0.z,p0.w,p1.x,p1.y,p1.z,p1.w};
                float bb[8] = {b0.x,b0.y,b0.z,b0.w,b1.x,b1.y,b1.z,b1.w};
#pragma unroll
                for (int i = 0; i < 8; i++)
#pragma unroll
                    for (int j = 0; j < 8; j++)
                        acc[i][j] = fmaf(aa[i], bb[j], acc[i][j]);
            }
        }
    }

    // epilogue: bias, per-row L2 norm across the block's full 128 cols
    if (t < 64) rowsq[t] = 0.f;
    __syncthreads();

    float bias[8];
#pragma unroll
    for (int j = 0; j < 8; j++) bias[j] = bl[tx * 8 + j];

#pragma unroll
    for (int i = 0; i < 8; i++) {
        float s = 0.f;
#pragma unroll
        for (int j = 0; j < 8; j++) {
            acc[i][j] += bias[j];
            s = fmaf(acc[i][j], acc[i][j], s);
        }
        atomicAdd(&rowsq[ty * 8 + i], s);
    }
    __syncthreads();

#pragma unroll
    for (int i = 0; i < 8; i++) {
        int r = row0 + ty * 8 + i;
        if (r >= n) continue;
        float inv = 1.0f / fmaxf(sqrtf(rowsq[ty * 8 + i]), 1e-12f);
        float4 o0, o1;
        o0.x = acc[i][0] * inv; o0.y = acc[i][1] * inv;
        o0.z = acc[i][2] * inv; o0.w = acc[i][3] * inv;
        o1.x = acc[i][4] * inv; o1.y = acc[i][5] * inv;
        o1.z = acc[i][6] * inv; o1.w = acc[i][7] * inv;
        if (LAYER == 1) {  // ReLU fused (reference: relu(normalized))
            o0.x = fmaxf(o0.x, 0.f); o0.y = fmaxf(o0.y, 0.f);
            o0.z = fmaxf(o0.z, 0.f); o0.w = fmaxf(o0.w, 0.f);
            o1.x = fmaxf(o1.x, 0.f); o1.y = fmaxf(o1.y, 0.f);
            o1.z = fmaxf(o1.z, 0.f); o1.w = fmaxf(o1.w, 0.f);
        }
        float4* op = reinterpret_cast<float4*>(out + (size_t)r * FDIM + tx * 8);
        op[0] = o0; op[1] = o1;
    }
}

// ---------------- BatchNorm ------------------------------------------------
__global__ void k_bnstats(int n) {
    int col = threadIdx.x;
    float s = 0.f, s2 = 0.f;
    for (int r = blockIdx.x; r < n; r += gridDim.x) {
        float v = g_h[(size_t)r * FDIM + col];
        s += v;
        s2 = fmaf(v, v, s2);
    }
    atomicAdd(&g_bn[col], s);
    atomicAdd(&g_bn[128 + col], s2);
}

__global__ void k_bncoef(const float* __restrict__ gamma,
                         const float* __restrict__ beta, float invn) {
    int t = threadIdx.x;
    float mu  = g_bn[t] * invn;
    float var = g_bn[128 + t] * invn - mu * mu;
    float a = gamma[t] * rsqrtf(fmaxf(var, 0.f) + 1e-5f);
    g_bnab[t]       = a;
    g_bnab[128 + t] = fmaf(-mu, a, beta[t]);
}

__global__ void k_bnapply(int n4) {
    int i = blockIdx.x * blockDim.x + threadIdx.x;
    if (i >= n4) return;
    int c = i & 31;
    float4 a  = reinterpret_cast<float4*>(g_bnab)[c];
    float4 sh = reinterpret_cast<float4*>(g_bnab)[32 + c];
    float4 v  = reinterpret_cast<float4*>(g_h)[i];
    v.x = fmaf(v.x, a.x, sh.x);
    v.y = fmaf(v.y, a.y, sh.y);
    v.z = fmaf(v.z, a.z, sh.z);
    v.w = fmaf(v.w, a.w, sh.w);
    reinterpret_cast<float4*>(g_h)[i] = v;
}

// ---------------- FC head: warp per row ------------------------------------
__global__ void k_fc(const float* __restrict__ W, const float* __restrict__ b,
                     float* __restrict__ out, int n) {
    __shared__ __align__(16) float Ws[8 * FDIM];
    int t = threadIdx.x;
    reinterpret_cast<float4*>(Ws)[t] = reinterpret_cast<const float4*>(W)[t];
    __syncthreads();

    int warp = (blockIdx.x * blockDim.x + t) >> 5;
    int lane = t & 31;
    if (warp >= n) return;

    float4 v = reinterpret_cast<const float4*>(g_h2 + (size_t)warp * FDIM)[lane];
    float acc[8];
#pragma unroll
    for (int j = 0; j < 8; j++) {
        float4 w = reinterpret_cast<float4*>(Ws)[j * 32 + lane];
        acc[j] = v.x * w.x + v.y * w.y + v.z * w.z + v.w * w.w;
    }
#pragma unroll
    for (int off = 16; off; off >>= 1)
#pragma unroll
        for (int j = 0; j < 8; j++)
            acc[j] += __shfl_down_sync(0xffffffffu, acc[j], off);
    if (lane == 0) {
#pragma unroll
        for (int j = 0; j < 8; j++)
            out[(size_t)warp * 8 + j] = acc[j] + b[j];
    }
}

// ---------------- launch ----------------------------------------------------
extern "C" void kernel_launch(void* const* d_in, const int* in_sizes, int n_in,
                              void* d_out, int out_size) {
    const float* x   = (const float*)d_in[0];
    const void*  ei  = d_in[1];
    const float* W1l = (const float*)d_in[2];
    const float* b1l = (const float*)d_in[3];
    const float* W1r = (const float*)d_in[4];
    const float* gma = (const float*)d_in[5];
    const float* bta = (const float*)d_in[6];
    const float* W2l = (const float*)d_in[7];
    const float* b2l = (const float*)d_in[8];
    const float* W2r = (const float*)d_in[9];
    const float* Wfc = (const float*)d_in[10];
    const float* bfc = (const float*)d_in[11];
    float* out = (float*)d_out;

    int n  = in_sizes[0] / FDIM;
    int E  = in_sizes[1] / 2;
    int n4 = n * (FDIM / 4);
    int zb = (n4 + 255) / 256;
    long long sth = (long long)E * 32;
    int sb = (int)((sth + 255) / 256);
    int gb = (n + 63) / 64;
    int fb = (n * 32 + 255) / 256;

    k_detect<<<1, 32>>>(ei);
    k_zero_all<<<zb, 256>>>(n4, n / 4);
    k_scatter<0, 1><<<sb, 256>>>(x, ei, E);
    k_sage<1><<<gb, 128>>>(x, W1l, b1l, W1r, n);
    k_bnstats<<<512, 128>>>(n);
    k_bncoef<<<1, 128>>>(gma, bta, 1.0f / (float)n);
    k_bnapply<<<zb, 256>>>(n4);
    k_zero_agg<<<zb, 256>>>(n4);
    k_scatter<1, 0><<<sb, 256>>>(x, ei, E);
    k_sage<2><<<gb, 128>>>(x, W2l, b2l, W2r, n);
    k_fc<<<fb, 256>>>(Wfc, bfc, out, n);
}

// round 2
// speedup vs baseline: 1.1696x; 1.1696x over previous
#include <cuda_runtime.h>

#define FDIM 128
#define NN   50000
#define EMAX 800000

// ---------------- scratch (device globals: no allocation allowed) ----------
static __device__ float g_agg[(size_t)NN * FDIM];
static __device__ float g_h  [(size_t)NN * FDIM];
static __device__ float g_h2 [(size_t)NN * FDIM];
static __device__ float g_bn [256];    // [0:128) sum, [128:256) sumsq
static __device__ float g_bnab[256];   // [0:128) scale, [128:256) shift
static __device__ int   g_cnt[NN];       // histogram
static __device__ int   g_rowptr[NN + 1];
static __device__ int   g_cursor[NN];
static __device__ int   g_srcs[EMAX];
static __device__ int   g_is64;

// ---------------- edge-index dtype detection -------------------------------
__global__ void k_detect(const void* ei) {
    if (threadIdx.x == 0) {
        const int* p = (const int*)ei;
        g_is64 = (p[1] == 0 && p[3] == 0) ? 1 : 0;   // int64 LE: high words zero
    }
}

__device__ __forceinline__ int edge_val(const void* ei, long long elem) {
    // element index into the flat [2, E] array; returns low 32 bits
    if (g_is64) return reinterpret_cast<const int*>(ei)[2 * elem];
    return reinterpret_cast<const int*>(ei)[elem];
}

// ---------------- zero: histogram + bn accumulators ------------------------
__global__ void k_zero(int n) {
    int i = blockIdx.x * blockDim.x + threadIdx.x;
    if (i < n)   g_cnt[i] = 0;
    if (i < 256) g_bn[i]  = 0.f;
}

// ---------------- CSR build -------------------------------------------------
__global__ void k_hist(const void* __restrict__ ei, int E) {
    int e = blockIdx.x * blockDim.x + threadIdx.x;
    if (e >= E) return;
    int d = edge_val(ei, (long long)E + e);
    atomicAdd(&g_cnt[d], 1);
}

__global__ void k_scan(int n) {
    __shared__ int s[1024];
    int t = threadIdx.x;
    int carry = 0;
    for (int base = 0; base < n; base += 1024) {
        int v = (base + t < n) ? g_cnt[base + t] : 0;
        s[t] = v;
        __syncthreads();
#pragma unroll
        for (int off = 1; off < 1024; off <<= 1) {
            int x = (t >= off) ? s[t - off] : 0;
            __syncthreads();
            s[t] += x;
            __syncthreads();
        }
        int excl = s[t] - v;
        if (base + t < n) {
            g_rowptr[base + t] = carry + excl;
            g_cursor[base + t] = carry + excl;
        }
        int total = s[1023];
        __syncthreads();
        carry += total;
    }
    if (t == 0) g_rowptr[n] = carry;
}

__global__ void k_permute(const void* __restrict__ ei, int E) {
    int e = blockIdx.x * blockDim.x + threadIdx.x;
    if (e >= E) return;
    int sidx = edge_val(ei, e);
    int d    = edge_val(ei, (long long)E + e);
    int pos  = atomicAdd(&g_cursor[d], 1);
    g_srcs[pos] = sidx;
}

// ---------------- aggregation: warp per dst row, gather-sum, fused mean ----
template<int SRC>
__global__ void k_agg(const float* __restrict__ xin, int n) {
    int w    = (blockIdx.x * blockDim.x + threadIdx.x) >> 5;
    int lane = threadIdx.x & 31;
    if (w >= n) return;
    const float* buf = (SRC == 0) ? xin : g_h;

    int beg = g_rowptr[w], end = g_rowptr[w + 1];
    float4 acc0 = make_float4(0.f, 0.f, 0.f, 0.f);
    float4 acc1 = acc0;

    for (int i = beg; i < end; i += 32) {
        int idx = (i + lane < end) ? g_srcs[i + lane] : 0;
        int cnt = min(32, end - i);
        int j = 0;
        for (; j + 2 <= cnt; j += 2) {
            int s0 = __shfl_sync(0xffffffffu, idx, j);
            int s1 = __shfl_sync(0xffffffffu, idx, j + 1);
            float4 v0 = reinterpret_cast<const float4*>(buf + (size_t)s0 * FDIM)[lane];
            float4 v1 = reinterpret_cast<const float4*>(buf + (size_t)s1 * FDIM)[lane];
            acc0.x += v0.x; acc0.y += v0.y; acc0.z += v0.z; acc0.w += v0.w;
            acc1.x += v1.x; acc1.y += v1.y; acc1.z += v1.z; acc1.w += v1.w;
        }
        if (j < cnt) {
            int s0 = __shfl_sync(0xffffffffu, idx, j);
            float4 v0 = reinterpret_cast<const float4*>(buf + (size_t)s0 * FDIM)[lane];
            acc0.x += v0.x; acc0.y += v0.y; acc0.z += v0.z; acc0.w += v0.w;
        }
    }
    float inv = (end > beg) ? 1.0f / (float)(end - beg) : 0.f;
    float4 o;
    o.x = (acc0.x + acc1.x) * inv;
    o.y = (acc0.y + acc1.y) * inv;
    o.z = (acc0.z + acc1.z) * inv;
    o.w = (acc0.w + acc1.w) * inv;
    reinterpret_cast<float4*>(g_agg + (size_t)w * FDIM)[lane] = o;
}

// ---------------- packed f32x2 helpers --------------------------------------
__device__ __forceinline__ unsigned long long pack2(float lo, float hi) {
    unsigned long long r;
    asm("mov.b64 %0, {%1, %2};" : "=l"(r)
        : "r"(__float_as_uint(lo)), "r"(__float_as_uint(hi)));
    return r;
}
__device__ __forceinline__ unsigned long long dup2(float v) {
    unsigned long long r;
    unsigned u = __float_as_uint(v);
    asm("mov.b64 %0, {%1, %1};" : "=l"(r) : "r"(u));
    return r;
}
__device__ __forceinline__ void fma2(unsigned long long& acc,
                                     unsigned long long a, unsigned long long b) {
    asm("fma.rn.f32x2 %0, %1, %2, %0;" : "+l"(acc) : "l"(a), "l"(b));
}
__device__ __forceinline__ void unpack2(unsigned long long p, float& lo, float& hi) {
    unsigned a, b;
    asm("mov.b64 {%0, %1}, %2;" : "=r"(a), "=r"(b) : "l"(p));
    lo = __uint_as_float(a); hi = __uint_as_float(b);
}

// ---------------- fused SAGE linear + bias + L2-norm (+ReLU) ---------------
// C[64 x 128] per block, 128 threads, 8x8 register tile each, FFMA2 inner loop.
// K = 256: branch 0 = g_agg (already mean'd) @ Wl^T, branch 1 = root @ Wr^T.
template<int LAYER>
__global__ __launch_bounds__(128)
void k_sage(const float* __restrict__ xin,
            const float* __restrict__ Wl, const float* __restrict__ bl,
            const float* __restrict__ Wr, int n) {
    __shared__ __align__(16) float As[16][64];
    __shared__ __align__(16) float Bs[16][128];
    __shared__ float rowsq[64];

    const float* A2  = (LAYER == 1) ? xin : g_h;
    float*       out = (LAYER == 1) ? g_h : g_h2;

    int t  = threadIdx.x;
    int tx = t & 15;        // col group (8 cols)
    int ty = t >> 4;        // row group (8 rows)
    int row0 = blockIdx.x * 64;

    int lrow = t >> 1;
    int lk   = (t & 1) * 8;
    int grow = row0 + lrow;

    unsigned long long acc[8][4];
#pragma unroll
    for (int i = 0; i < 8; i++)
#pragma unroll
        for (int j = 0; j < 4; j++) acc[i][j] = 0ull;

#pragma unroll 1
    for (int br = 0; br < 2; br++) {
        const float* A = (br == 0) ? g_agg : A2;
        const float* W = (br == 0) ? Wl : Wr;
#pragma unroll 1
        for (int kt = 0; kt < FDIM; kt += 16) {
            float4 a0 = make_float4(0.f,0.f,0.f,0.f), a1 = a0;
            if (grow < n) {
                const float4* ap = reinterpret_cast<const float4*>(
                    A + (size_t)grow * FDIM + kt + lk);
                a0 = ap[0]; a1 = ap[1];
            }
            const float4* wp = reinterpret_cast<const float4*>(W + t * FDIM + kt);
            float4 w0 = wp[0], w1 = wp[1], w2 = wp[2], w3 = wp[3];

            __syncthreads();
            As[lk+0][lrow] = a0.x; As[lk+1][lrow] = a0.y;
            As[lk+2][lrow] = a0.z; As[lk+3][lrow] = a0.w;
            As[lk+4][lrow] = a1.x; As[lk+5][lrow] = a1.y;
            As[lk+6][lrow] = a1.z; As[lk+7][lrow] = a1.w;

            Bs[ 0][t] = w0.x; Bs[ 1][t] = w0.y; Bs[ 2][t] = w0.z; Bs[ 3][t] = w0.w;
            Bs[ 4][t] = w1.x; Bs[ 5][t] = w1.y; Bs[ 6][t] = w1.z; Bs[ 7][t] = w1.w;
            Bs[ 8][t] = w2.x; Bs[ 9][t] = w2.y; Bs[10][t] = w2.z; Bs[11][t] = w2.w;
            Bs[12][t] = w3.x; Bs[13][t] = w3.y; Bs[14][t] = w3.z; Bs[15][t] = w3.w;
            __syncthreads();

#pragma unroll
            for (int k = 0; k < 16; k++) {
                float4 b0 = *reinterpret_cast<const float4*>(&Bs[k][tx * 8]);
                float4 b1 = *reinterpret_cast<const float4*>(&Bs[k][tx * 8 + 4]);
                float4 p0 = *reinterpret_cast<const float4*>(&As[k][ty * 8]);
                float4 p1 = *reinterpret_cast<const float4*>(&As[k][ty * 8 + 4]);
                unsigned long long bp[4];
                bp[0] = pack2(b0.x, b0.y); bp[1] = pack2(b0.z, b0.w);
                bp[2] = pack2(b1.x, b1.y); bp[3] = pack2(b1.z, b1.w);
                float aa[8] = {p0.x,p0.y,p0.z,p0.w,p1.x,p1.y,p1.z,p1.w};
#pragma unroll
                for (int i = 0; i < 8; i++) {
                    unsigned long long ad = dup2(aa[i]);
#pragma unroll
                    for (int j = 0; j < 4; j++) fma2(acc[i][j], ad, bp[j]);
                }
            }
        }
    }

    // epilogue: bias, per-row L2 norm across the block's full 128 cols
    if (t < 64) rowsq[t] = 0.f;
    __syncthreads();

    float bias[8];
#pragma unroll
    for (int j = 0; j < 8; j++) bias[j] = bl[tx * 8 + j];

    float o[8][8];
#pragma unroll
    for (int i = 0; i < 8; i++) {
        float s = 0.f;
#pragma unroll
        for (int j = 0; j < 4; j++) {
            float lo, hi;
            unpack2(acc[i][j], lo, hi);
            lo += bias[2*j]; hi += bias[2*j+1];
            o[i][2*j] = lo; o[i][2*j+1] = hi;
            s = fmaf(lo, lo, s);
            s = fmaf(hi, hi, s);
        }
        atomicAdd(&rowsq[ty * 8 + i], s);
    }
    __syncthreads();

#pragma unroll
    for (int i = 0; i < 8; i++) {
        int r = row0 + ty * 8 + i;
        if (r >= n) continue;
        float inv = 1.0f / fmaxf(sqrtf(rowsq[ty * 8 + i]), 1e-12f);
        float4 o0, o1;
        o0.x = o[i][0] * inv; o0.y = o[i][1] * inv;
        o0.z = o[i][2] * inv; o0.w = o[i][3] * inv;
        o1.x = o[i][4] * inv; o1.y = o[i][5] * inv;
        o1.z = o[i][6] * inv; o1.w = o[i][7] * inv;
        if (LAYER == 1) {  // ReLU fused (reference: relu(normalized))
            o0.x = fmaxf(o0.x, 0.f); o0.y = fmaxf(o0.y, 0.f);
            o0.z = fmaxf(o0.z, 0.f); o0.w = fmaxf(o0.w, 0.f);
            o1.x = fmaxf(o1.x, 0.f); o1.y = fmaxf(o1.y, 0.f);
            o1.z = fmaxf(o1.z, 0.f); o1.w = fmaxf(o1.w, 0.f);
        }
        float4* op = reinterpret_cast<float4*>(out + (size_t)r * FDIM + tx * 8);
        op[0] = o0; op[1] = o1;
    }
}

// ---------------- BatchNorm ------------------------------------------------
__global__ void k_bnstats(int n) {
    int col = threadIdx.x;
    float s = 0.f, s2 = 0.f;
    for (int r = blockIdx.x; r < n; r += gridDim.x) {
        float v = g_h[(size_t)r * FDIM + col];
        s += v;
        s2 = fmaf(v, v, s2);
    }
    atomicAdd(&g_bn[col], s);
    atomicAdd(&g_bn[128 + col], s2);
}

__global__ void k_bncoef(const float* __restrict__ gamma,
                         const float* __restrict__ beta, float invn) {
    int t = threadIdx.x;
    float mu  = g_bn[t] * invn;
    float var = g_bn[128 + t] * invn - mu * mu;
    float a = gamma[t] * rsqrtf(fmaxf(var, 0.f) + 1e-5f);
    g_bnab[t]       = a;
    g_bnab[128 + t] = fmaf(-mu, a, beta[t]);
}

__global__ void k_bnapply(int n4) {
    int i = blockIdx.x * blockDim.x + threadIdx.x;
    if (i >= n4) return;
    int c = i & 31;
    float4 a  = reinterpret_cast<float4*>(g_bnab)[c];
    float4 sh = reinterpret_cast<float4*>(g_bnab)[32 + c];
    float4 v  = reinterpret_cast<float4*>(g_h)[i];
    v.x = fmaf(v.x, a.x, sh.x);
    v.y = fmaf(v.y, a.y, sh.y);
    v.z = fmaf(v.z, a.z, sh.z);
    v.w = fmaf(v.w, a.w, sh.w);
    reinterpret_cast<float4*>(g_h)[i] = v;
}

// ---------------- FC head: warp per row ------------------------------------
__global__ void k_fc(const float* __restrict__ W, const float* __restrict__ b,
                     float* __restrict__ out, int n) {
    __shared__ __align__(16) float Ws[8 * FDIM];
    int t = threadIdx.x;
    reinterpret_cast<float4*>(Ws)[t] = reinterpret_cast<const float4*>(W)[t];
    __syncthreads();

    int warp = (blockIdx.x * blockDim.x + t) >> 5;
    int lane = t & 31;
    if (warp >= n) return;

    float4 v = reinterpret_cast<const float4*>(g_h2 + (size_t)warp * FDIM)[lane];
    float acc[8];
#pragma unroll
    for (int j = 0; j < 8; j++) {
        float4 w = reinterpret_cast<float4*>(Ws)[j * 32 + lane];
        acc[j] = v.x * w.x + v.y * w.y + v.z * w.z + v.w * w.w;
    }
#pragma unroll
    for (int off = 16; off; off >>= 1)
#pragma unroll
        for (int j = 0; j < 8; j++)
            acc[j] += __shfl_down_sync(0xffffffffu, acc[j], off);
    if (lane == 0) {
#pragma unroll
        for (int j = 0; j < 8; j++)
            out[(size_t)warp * 8 + j] = acc[j] + b[j];
    }
}

// ---------------- launch ----------------------------------------------------
extern "C" void kernel_launch(void* const* d_in, const int* in_sizes, int n_in,
                              void* d_out, int out_size) {
    const float* x   = (const float*)d_in[0];
    const void*  ei  = d_in[1];
    const float* W1l = (const float*)d_in[2];
    const float* b1l = (const float*)d_in[3];
    const float* W1r = (const float*)d_in[4];
    const float* gma = (const float*)d_in[5];
    const float* bta = (const float*)d_in[6];
    const float* W2l = (const float*)d_in[7];
    const float* b2l = (const float*)d_in[8];
    const float* W2r = (const float*)d_in[9];
    const float* Wfc = (const float*)d_in[10];
    const float* bfc = (const float*)d_in[11];
    float* out = (float*)d_out;

    int n  = in_sizes[0] / FDIM;
    int E  = in_sizes[1] / 2;
    int n4 = n * (FDIM / 4);
    int zb = (n + 255) / 256;
    int eb = (E + 255) / 256;
    int gb = (n + 63) / 64;
    int ab = (n * 32 + 255) / 256;
    int fb = (n * 32 + 255) / 256;
    int bb = (n4 + 255) / 256;

    k_detect<<<1, 32>>>(ei);
    k_zero<<<zb, 256>>>(n);
    k_hist<<<eb, 256>>>(ei, E);
    k_scan<<<1, 1024>>>(n);
    k_permute<<<eb, 256>>>(ei, E);
    k_agg<0><<<ab, 256>>>(x, n);
    k_sage<1><<<gb, 128>>>(x, W1l, b1l, W1r, n);
    k_bnstats<<<512, 128>>>(n);
    k_bncoef<<<1, 128>>>(gma, bta, 1.0f / (float)n);
    k_bnapply<<<bb, 256>>>(n4);
    k_agg<1><<<ab, 256>>>(x, n);
    k_sage<2><<<gb, 128>>>(x, W2l, b2l, W2r, n);
    k_fc<<<fb, 256>>>(Wfc, bfc, out, n);
}

// round 3
// speedup vs baseline: 1.3669x; 1.1686x over previous
#include <cuda_runtime.h>

#define FDIM 128
#define NN   50000
#define EMAX 800000
#define NBMAX 64   // max scan blocks: ceil(50000/1024)=49

// ---------------- scratch (device globals: no allocation allowed) ----------
static __device__ float g_agg[(size_t)NN * FDIM];
static __device__ float g_h  [(size_t)NN * FDIM];
static __device__ float g_h2 [(size_t)NN * FDIM];
static __device__ float g_bn [256];    // [0:128) sum, [128:256) sumsq
static __device__ float g_bnab[256];   // [0:128) scale, [128:256) shift
static __device__ int   g_cnt[NN];       // histogram
static __device__ int   g_rowptr[NN + 1];
static __device__ int   g_cursor[NN];
static __device__ int   g_srcs[EMAX];
static __device__ int   g_bsum[NBMAX];
static __device__ int   g_boff[NBMAX + 1];
static __device__ int   g_is64;

// ---------------- edge-index dtype detection -------------------------------
__global__ void k_detect(const void* ei) {
    if (threadIdx.x == 0) {
        const int* p = (const int*)ei;
        g_is64 = (p[1] == 0 && p[3] == 0) ? 1 : 0;   // int64 LE: high words zero
    }
}

__device__ __forceinline__ int edge_val(const void* ei, long long elem) {
    if (g_is64) return reinterpret_cast<const int*>(ei)[2 * elem];
    return reinterpret_cast<const int*>(ei)[elem];
}

// ---------------- zero: histogram + bn accumulators ------------------------
__global__ void k_zero(int n) {
    int i = blockIdx.x * blockDim.x + threadIdx.x;
    if (i < n)   g_cnt[i] = 0;
    if (i < 256) g_bn[i]  = 0.f;
}

// ---------------- CSR build -------------------------------------------------
__global__ void k_hist(const void* __restrict__ ei, int E) {
    int e = blockIdx.x * blockDim.x + threadIdx.x;
    if (e >= E) return;
    int d = edge_val(ei, (long long)E + e);
    atomicAdd(&g_cnt[d], 1);
}

// phase 1: per-block exclusive scan (1024 threads, shfl warp scans)
__global__ __launch_bounds__(1024) void k_scan1(int n) {
    __shared__ int warpsum[32];
    int t = threadIdx.x;
    int i = blockIdx.x * 1024 + t;
    int lane = t & 31, wid = t >> 5;

    int v = (i < n) ? g_cnt[i] : 0;
    int x = v;
#pragma unroll
    for (int o = 1; o < 32; o <<= 1) {
        int y = __shfl_up_sync(0xffffffffu, x, o);
        if (lane >= o) x += y;
    }
    if (lane == 31) warpsum[wid] = x;
    __syncthreads();
    if (wid == 0) {
        int s = warpsum[lane];
#pragma unroll
        for (int o = 1; o < 32; o <<= 1) {
            int y = __shfl_up_sync(0xffffffffu, s, o);
            if (lane >= o) s += y;
        }
        warpsum[lane] = s;
    }
    __syncthreads();
    int base = (wid > 0) ? warpsum[wid - 1] : 0;
    int incl = base + x;
    if (i < n) g_rowptr[i] = incl - v;          // exclusive within block
    if (t == 1023) g_bsum[blockIdx.x] = incl;   // block total
}

// phase 2: scan block totals (tiny: <= 49 values)
__global__ void k_scan2(int nb) {
    if (threadIdx.x == 0) {
        int run = 0;
        for (int b = 0; b < nb; b++) { g_boff[b] = run; run += g_bsum[b]; }
        g_boff[nb] = run;
    }
}

// phase 3: add block offsets, fill cursor, set rowptr[n]
__global__ __launch_bounds__(1024) void k_scan3(int n, int nb) {
    int i = blockIdx.x * 1024 + threadIdx.x;
    if (i < n) {
        int v = g_rowptr[i] + g_boff[blockIdx.x];
        g_rowptr[i] = v;
        g_cursor[i] = v;
    }
    if (i == 0) g_rowptr[n] = g_boff[nb];
}

__global__ void k_permute(const void* __restrict__ ei, int E) {
    int e = blockIdx.x * blockDim.x + threadIdx.x;
    if (e >= E) return;
    int sidx = edge_val(ei, e);
    int d    = edge_val(ei, (long long)E + e);
    int pos  = atomicAdd(&g_cursor[d], 1);
    g_srcs[pos] = sidx;
}

// ---------------- aggregation: warp per dst row, gather-sum, fused mean ----
template<int SRC>
__global__ void k_agg(const float* __restrict__ xin, int n) {
    int w    = (blockIdx.x * blockDim.x + threadIdx.x) >> 5;
    int lane = threadIdx.x & 31;
    if (w >= n) return;
    const float* buf = (SRC == 0) ? xin : g_h;

    int beg = g_rowptr[w], end = g_rowptr[w + 1];
    float4 acc0 = make_float4(0.f, 0.f, 0.f, 0.f);
    float4 acc1 = acc0;

    for (int i = beg; i < end; i += 32) {
        int idx = (i + lane < end) ? g_srcs[i + lane] : 0;
        int cnt = min(32, end - i);
        int j = 0;
        for (; j + 2 <= cnt; j += 2) {
            int s0 = __shfl_sync(0xffffffffu, idx, j);
            int s1 = __shfl_sync(0xffffffffu, idx, j + 1);
            float4 v0 = reinterpret_cast<const float4*>(buf + (size_t)s0 * FDIM)[lane];
            float4 v1 = reinterpret_cast<const float4*>(buf + (size_t)s1 * FDIM)[lane];
            acc0.x += v0.x; acc0.y += v0.y; acc0.z += v0.z; acc0.w += v0.w;
            acc1.x += v1.x; acc1.y += v1.y; acc1.z += v1.z; acc1.w += v1.w;
        }
        if (j < cnt) {
            int s0 = __shfl_sync(0xffffffffu, idx, j);
            float4 v0 = reinterpret_cast<const float4*>(buf + (size_t)s0 * FDIM)[lane];
            acc0.x += v0.x; acc0.y += v0.y; acc0.z += v0.z; acc0.w += v0.w;
        }
    }
    float inv = (end > beg) ? 1.0f / (float)(end - beg) : 0.f;
    float4 o;
    o.x = (acc0.x + acc1.x) * inv;
    o.y = (acc0.y + acc1.y) * inv;
    o.z = (acc0.z + acc1.z) * inv;
    o.w = (acc0.w + acc1.w) * inv;
    reinterpret_cast<float4*>(g_agg + (size_t)w * FDIM)[lane] = o;
}

// ---------------- packed f32x2 helpers --------------------------------------
__device__ __forceinline__ unsigned long long pack2(float lo, float hi) {
    unsigned long long r;
    asm("mov.b64 %0, {%1, %2};" : "=l"(r)
        : "r"(__float_as_uint(lo)), "r"(__float_as_uint(hi)));
    return r;
}
__device__ __forceinline__ unsigned long long dup2(float v) {
    unsigned long long r;
    unsigned u = __float_as_uint(v);
    asm("mov.b64 %0, {%1, %1};" : "=l"(r) : "r"(u));
    return r;
}
__device__ __forceinline__ void fma2(unsigned long long& acc,
                                     unsigned long long a, unsigned long long b) {
    asm("fma.rn.f32x2 %0, %1, %2, %0;" : "+l"(acc) : "l"(a), "l"(b));
}
__device__ __forceinline__ void unpack2(unsigned long long p, float& lo, float& hi) {
    unsigned a, b;
    asm("mov.b64 {%0, %1}, %2;" : "=r"(a), "=r"(b) : "l"(p));
    lo = __uint_as_float(a); hi = __uint_as_float(b);
}

// ---------------- fused SAGE linear + bias + L2-norm (+ReLU) ---------------
// C[64 x 128] per block, 128 threads, 8x8 register tile each, FFMA2 inner loop.
// K = 256: branch 0 = g_agg (already mean'd) @ Wl^T, branch 1 = root @ Wr^T.
template<int LAYER>
__global__ __launch_bounds__(128)
void k_sage(const float* __restrict__ xin,
            const float* __restrict__ Wl, const float* __restrict__ bl,
            const float* __restrict__ Wr, int n) {
    __shared__ __align__(16) float As[16][64];
    __shared__ __align__(16) float Bs[16][128];
    __shared__ float rowsq[64];

    const float* A2  = (LAYER == 1) ? xin : g_h;
    float*       out = (LAYER == 1) ? g_h : g_h2;

    int t  = threadIdx.x;
    int tx = t & 15;        // col group (8 cols)
    int ty = t >> 4;        // row group (8 rows)
    int row0 = blockIdx.x * 64;

    int lrow = t >> 1;
    int lk   = (t & 1) * 8;
    int grow = row0 + lrow;

    unsigned long long acc[8][4];
#pragma unroll
    for (int i = 0; i < 8; i++)
#pragma unroll
        for (int j = 0; j < 4; j++) acc[i][j] = 0ull;

#pragma unroll 1
    for (int br = 0; br < 2; br++) {
        const float* A = (br == 0) ? g_agg : A2;
        const float* W = (br == 0) ? Wl : Wr;
#pragma unroll 1
        for (int kt = 0; kt < FDIM; kt += 16) {
            float4 a0 = make_float4(0.f,0.f,0.f,0.f), a1 = a0;
            if (grow < n) {
                const float4* ap = reinterpret_cast<const float4*>(
                    A + (size_t)grow * FDIM + kt + lk);
                a0 = ap[0]; a1 = ap[1];
            }
            const float4* wp = reinterpret_cast<const float4*>(W + t * FDIM + kt);
            float4 w0 = wp[0], w1 = wp[1], w2 = wp[2], w3 = wp[3];

            __syncthreads();
            As[lk+0][lrow] = a0.x; As[lk+1][lrow] = a0.y;
            As[lk+2][lrow] = a0.z; As[lk+3][lrow] = a0.w;
            As[lk+4][lrow] = a1.x; As[lk+5][lrow] = a1.y;
            As[lk+6][lrow] = a1.z; As[lk+7][lrow] = a1.w;

            Bs[ 0][t] = w0.x; Bs[ 1][t] = w0.y; Bs[ 2][t] = w0.z; Bs[ 3][t] = w0.w;
            Bs[ 4][t] = w1.x; Bs[ 5][t] = w1.y; Bs[ 6][t] = w1.z; Bs[ 7][t] = w1.w;
            Bs[ 8][t] = w2.x; Bs[ 9][t] = w2.y; Bs[10][t] = w2.z; Bs[11][t] = w2.w;
            Bs[12][t] = w3.x; Bs[13][t] = w3.y; Bs[14][t] = w3.z; Bs[15][t] = w3.w;
            __syncthreads();

#pragma unroll
            for (int k = 0; k < 16; k++) {
                float4 b0 = *reinterpret_cast<const float4*>(&Bs[k][tx * 8]);
                float4 b1 = *reinterpret_cast<const float4*>(&Bs[k][tx * 8 + 4]);
                float4 p0 = *reinterpret_cast<const float4*>(&As[k][ty * 8]);
                float4 p1 = *reinterpret_cast<const float4*>(&As[k][ty * 8 + 4]);
                unsigned long long bp[4];
                bp[0] = pack2(b0.x, b0.y); bp[1] = pack2(b0.z, b0.w);
                bp[2] = pack2(b1.x, b1.y); bp[3] = pack2(b1.z, b1.w);
                float aa[8] = {p0.x,p0.y,p0.z,p0.w,p1.x,p1.y,p1.z,p1.w};
#pragma unroll
                for (int i = 0; i < 8; i++) {
                    unsigned long long ad = dup2(aa[i]);
#pragma unroll
                    for (int j = 0; j < 4; j++) fma2(acc[i][j], ad, bp[j]);
                }
            }
        }
    }

    // epilogue: bias, per-row L2 norm across the block's full 128 cols
    if (t < 64) rowsq[t] = 0.f;
    __syncthreads();

    float bias[8];
#pragma unroll
    for (int j = 0; j < 8; j++) bias[j] = bl[tx * 8 + j];

    float o[8][8];
#pragma unroll
    for (int i = 0; i < 8; i++) {
        float s = 0.f;
#pragma unroll
        for (int j = 0; j < 4; j++) {
            float lo, hi;
            unpack2(acc[i][j], lo, hi);
            lo += bias[2*j]; hi += bias[2*j+1];
            o[i][2*j] = lo; o[i][2*j+1] = hi;
            s = fmaf(lo, lo, s);
            s = fmaf(hi, hi, s);
        }
        atomicAdd(&rowsq[ty * 8 + i], s);
    }
    __syncthreads();

#pragma unroll
    for (int i = 0; i < 8; i++) {
        int r = row0 + ty * 8 + i;
        if (r >= n) continue;
        float inv = 1.0f / fmaxf(sqrtf(rowsq[ty * 8 + i]), 1e-12f);
        float4 o0, o1;
        o0.x = o[i][0] * inv; o0.y = o[i][1] * inv;
        o0.z = o[i][2] * inv; o0.w = o[i][3] * inv;
        o1.x = o[i][4] * inv; o1.y = o[i][5] * inv;
        o1.z = o[i][6] * inv; o1.w = o[i][7] * inv;
        if (LAYER == 1) {
            o0.x = fmaxf(o0.x, 0.f); o0.y = fmaxf(o0.y, 0.f);
            o0.z = fmaxf(o0.z, 0.f); o0.w = fmaxf(o0.w, 0.f);
            o1.x = fmaxf(o1.x, 0.f); o1.y = fmaxf(o1.y, 0.f);
            o1.z = fmaxf(o1.z, 0.f); o1.w = fmaxf(o1.w, 0.f);
        }
        float4* op = reinterpret_cast<float4*>(out + (size_t)r * FDIM + tx * 8);
        op[0] = o0; op[1] = o1;
    }
}

// ---------------- BatchNorm ------------------------------------------------
__global__ void k_bnstats(int n) {
    int col = threadIdx.x;
    float s = 0.f, s2 = 0.f;
    for (int r = blockIdx.x; r < n; r += gridDim.x) {
        float v = g_h[(size_t)r * FDIM + col];
        s += v;
        s2 = fmaf(v, v, s2);
    }
    atomicAdd(&g_bn[col], s);
    atomicAdd(&g_bn[128 + col], s2);
}

__global__ void k_bncoef(const float* __restrict__ gamma,
                         const float* __restrict__ beta, float invn) {
    int t = threadIdx.x;
    float mu  = g_bn[t] * invn;
    float var = g_bn[128 + t] * invn - mu * mu;
    float a = gamma[t] * rsqrtf(fmaxf(var, 0.f) + 1e-5f);
    g_bnab[t]       = a;
    g_bnab[128 + t] = fmaf(-mu, a, beta[t]);
}

__global__ void k_bnapply(int n4) {
    int i = blockIdx.x * blockDim.x + threadIdx.x;
    if (i >= n4) return;
    int c = i & 31;
    float4 a  = reinterpret_cast<float4*>(g_bnab)[c];
    float4 sh = reinterpret_cast<float4*>(g_bnab)[32 + c];
    float4 v  = reinterpret_cast<float4*>(g_h)[i];
    v.x = fmaf(v.x, a.x, sh.x);
    v.y = fmaf(v.y, a.y, sh.y);
    v.z = fmaf(v.z, a.z, sh.z);
    v.w = fmaf(v.w, a.w, sh.w);
    reinterpret_cast<float4*>(g_h)[i] = v;
}

// ---------------- FC head: warp per row ------------------------------------
__global__ void k_fc(const float* __restrict__ W, const float* __restrict__ b,
                     float* __restrict__ out, int n) {
    __shared__ __align__(16) float Ws[8 * FDIM];
    int t = threadIdx.x;
    reinterpret_cast<float4*>(Ws)[t] = reinterpret_cast<const float4*>(W)[t];
    __syncthreads();

    int warp = (blockIdx.x * blockDim.x + t) >> 5;
    int lane = t & 31;
    if (warp >= n) return;

    float4 v = reinterpret_cast<const float4*>(g_h2 + (size_t)warp * FDIM)[lane];
    float acc[8];
#pragma unroll
    for (int j = 0; j < 8; j++) {
        float4 w = reinterpret_cast<float4*>(Ws)[j * 32 + lane];
        acc[j] = v.x * w.x + v.y * w.y + v.z * w.z + v.w * w.w;
    }
#pragma unroll
    for (int off = 16; off; off >>= 1)
#pragma unroll
        for (int j = 0; j < 8; j++)
            acc[j] += __shfl_down_sync(0xffffffffu, acc[j], off);
    if (lane == 0) {
#pragma unroll
        for (int j = 0; j < 8; j++)
            out[(size_t)warp * 8 + j] = acc[j] + b[j];
    }
}

// ---------------- launch ----------------------------------------------------
extern "C" void kernel_launch(void* const* d_in, const int* in_sizes, int n_in,
                              void* d_out, int out_size) {
    const float* x   = (const float*)d_in[0];
    const void*  ei  = d_in[1];
    const float* W1l = (const float*)d_in[2];
    const float* b1l = (const float*)d_in[3];
    const float* W1r = (const float*)d_in[4];
    const float* gma = (const float*)d_in[5];
    const float* bta = (const float*)d_in[6];
    const float* W2l = (const float*)d_in[7];
    const float* b2l = (const float*)d_in[8];
    const float* W2r = (const float*)d_in[9];
    const float* Wfc = (const float*)d_in[10];
    const float* bfc = (const float*)d_in[11];
    float* out = (float*)d_out;

    int n  = in_sizes[0] / FDIM;
    int E  = in_sizes[1] / 2;
    int n4 = n * (FDIM / 4);
    int zb = (n + 255) / 256;
    int eb = (E + 255) / 256;
    int gb = (n + 63) / 64;
    int ab = (n * 32 + 255) / 256;
    int fb = (n * 32 + 255) / 256;
    int bb = (n4 + 255) / 256;
    int nb = (n + 1023) / 1024;

    k_detect<<<1, 32>>>(ei);
    k_zero<<<zb, 256>>>(n);
    k_hist<<<eb, 256>>>(ei, E);
    k_scan1<<<nb, 1024>>>(n);
    k_scan2<<<1, 32>>>(nb);
    k_scan3<<<nb, 1024>>>(n, nb);
    k_permute<<<eb, 256>>>(ei, E);
    k_agg<0><<<ab, 256>>>(x, n);
    k_sage<1><<<gb, 128>>>(x, W1l, b1l, W1r, n);
    k_bnstats<<<512, 128>>>(n);
    k_bncoef<<<1, 128>>>(gma, bta, 1.0f / (float)n);
    k_bnapply<<<bb, 256>>>(n4);
    k_agg<1><<<ab, 256>>>(x, n);
    k_sage<2><<<gb, 128>>>(x, W2l, b2l, W2r, n);
    k_fc<<<fb, 256>>>(Wfc, bfc, out, n);
}